// round 9
// baseline (speedup 1.0000x reference)
#include <cuda_runtime.h>

// AnnularDilatedKNN: B=4, N=4096, C=64, SAMPLE=16, DILATED_RATE=2 -> NSAMPLE=32, K_out=16
// radius^2 = 256.
//
// R9: 2-D (z,y) cell grid (20x20, width 17), block-per-(batch,cell,half).
//  - all queries of a cell share one 3x3-cell neighborhood = 3 contiguous runs
//    of the (zslab,yslab)-sorted array; warps scan them with coalesced LDG.128
//    (no smem staging -> smem 16KB -> full occupancy, L1-resident data).
//  - hits -> per-warp bitmap over ORIGINAL ids (g_sid read only on hit);
//    selection = verified popc-prefix + binary search, ranks {0,16..30},
//    pad with center.
//  - build: count/scan/scatter, no global atomics. Gathers unchanged.
// Predicate + sq arithmetic byte-identical to all rel_err=0.0 kernels.

#define NB     4
#define NP     4096
#define KOUT   16
#define NCY    20
#define NCZ    20
#define NCELL2 (NCY * NCZ)          // 400
#define CMIN   (-170.0f)
#define INVC   (1.0f / 17.0f)
#define QW     16                   // warps per query block
#define SPLIT  2                    // query blocks per cell
#define CBLK   64                   // count/scatter blocks (256 thr), 16 per batch

__device__ float4 g_cand[NB * NP];           // cell-sorted (x,y,z,sq)
__device__ int    g_sid[NB * NP];            // original index per sorted slot
__device__ int    g_pcell[NB * NP];          // cell per original point
__device__ int    g_blkcnt[CBLK * NCELL2];
__device__ int    g_blkbase[CBLK * NCELL2];
__device__ int    g_cstart[NB * (NCELL2 + 1)];
__device__ int    g_ids[NB * NP * KOUT];

__device__ __forceinline__ float sq3(float x, float y, float z) {
    // jnp.sum(xyz*xyz, -1): left-to-right, separately rounded products (no fma).
    return __fadd_rn(__fadd_rn(__fmul_rn(x, x), __fmul_rn(y, y)), __fmul_rn(z, z));
}

__device__ __forceinline__ int cell1(float v) {
    int c = (int)floorf(__fmul_rn(__fadd_rn(v, -CMIN), INVC));
    return min(max(c, 0), NCY - 1);
}

// ---- build 1: per-block cell counts ----
__global__ __launch_bounds__(256) void count_kernel(const float* __restrict__ xyz) {
    __shared__ int sc[NCELL2];
    const int i = blockIdx.x * 256 + threadIdx.x;
    for (int k = threadIdx.x; k < NCELL2; k += 256) sc[k] = 0;
    __syncthreads();
    const float y = xyz[3 * i + 1];
    const float z = xyz[3 * i + 2];
    const int c = cell1(z) * NCY + cell1(y);
    g_pcell[i] = c;
    atomicAdd(&sc[c], 1);
    __syncthreads();
    for (int k = threadIdx.x; k < NCELL2; k += 256)
        g_blkcnt[blockIdx.x * NCELL2 + k] = sc[k];
}

// ---- build 2: per-batch exclusive scan over 400 cells + per-block bases ----
__global__ __launch_bounds__(512) void scan_kernel() {
    __shared__ int wsum[16];
    const int b = blockIdx.x;
    const int tid = threadIdx.x, lane = tid & 31, wid = tid >> 5;

    int cnts[16];
    int tot = 0;
    if (tid < NCELL2) {
        #pragma unroll
        for (int k = 0; k < 16; ++k) {
            cnts[k] = g_blkcnt[(b * 16 + k) * NCELL2 + tid];
            tot += cnts[k];
        }
    }
    int incl = (tid < NCELL2) ? tot : 0;
    #pragma unroll
    for (int off = 1; off < 32; off <<= 1) {
        const int t = __shfl_up_sync(0xffffffffu, incl, off);
        if (lane >= off) incl += t;
    }
    if (lane == 31) wsum[wid] = incl;
    __syncthreads();
    if (wid == 0 && lane < 16) {
        int wv = wsum[lane];
        int wi = wv;
        #pragma unroll
        for (int off = 1; off < 16; off <<= 1) {
            const int t = __shfl_up_sync(0x0000ffffu, wi, off);
            if (lane >= off) wi += t;
        }
        wsum[lane] = wi - wv;
    }
    __syncthreads();
    if (tid < NCELL2) {
        const int excl = (incl - tot) + wsum[wid];
        g_cstart[b * (NCELL2 + 1) + tid] = excl;
        if (tid == NCELL2 - 1) g_cstart[b * (NCELL2 + 1) + NCELL2] = excl + tot; // == NP
        int run = excl;
        #pragma unroll
        for (int k = 0; k < 16; ++k) {
            g_blkbase[(b * 16 + k) * NCELL2 + tid] = run;
            run += cnts[k];
        }
    }
}

// ---- build 3: scatter into cell-sorted order (smem atomics only) ----
__global__ __launch_bounds__(256) void scatter_kernel(const float* __restrict__ xyz) {
    __shared__ int sc[NCELL2];
    __shared__ int sb[NCELL2];
    const int i = blockIdx.x * 256 + threadIdx.x;
    const int b = i >> 12;
    for (int k = threadIdx.x; k < NCELL2; k += 256) {
        sc[k] = 0;
        sb[k] = g_blkbase[blockIdx.x * NCELL2 + k];
    }
    __syncthreads();
    const int c = g_pcell[i];
    const int lr = atomicAdd(&sc[c], 1);
    const float x = xyz[3 * i + 0];
    const float y = xyz[3 * i + 1];
    const float z = xyz[3 * i + 2];
    const int gi = (b << 12) + sb[c] + lr;
    g_cand[gi] = make_float4(x, y, z, sq3(x, y, z));
    g_sid[gi] = i & (NP - 1);
}

// ---- query: block per (batch, cell, half); warp per query ----
__global__ __launch_bounds__(32 * QW) void query_kernel() {
    __shared__ unsigned bm[QW][128];
    __shared__ int cum[QW][128];

    const int g = blockIdx.x;
    const int half = g & (SPLIT - 1);
    const int cb = g / SPLIT;
    const int b = cb / NCELL2;
    const int cell = cb % NCELL2;
    const int cz = cell / NCY, cy = cell % NCY;
    const int bb = b << 12;

    const int* __restrict__ cs = g_cstart + b * (NCELL2 + 1);
    const int qs = cs[cell], qe = cs[cell + 1];
    const int warp = threadIdx.x >> 5, lane = threadIdx.x & 31;

    // 3 contiguous neighborhood runs (one per z-slab row)
    const int ylo = max(cy - 1, 0), yhi = min(cy + 1, NCY - 1);
    const int zlo = max(cz - 1, 0), zhi = min(cz + 1, NCZ - 1);
    int seg_s[3], seg_e[3];
    int nseg = 0;
    for (int zz = zlo; zz <= zhi; ++zz) {
        seg_s[nseg] = cs[zz * NCY + ylo];
        seg_e[nseg] = cs[zz * NCY + yhi + 1];
        ++nseg;
    }

    const float4* __restrict__ cand = g_cand + bb;
    const int* __restrict__ sid = g_sid + bb;

    for (int j = qs + half * QW + warp; j < qe; j += SPLIT * QW) {
        const float4 qc = cand[j];
        const int qn = sid[j];
        const float xn = qc.x, yn = qc.y, zn = qc.z, sqn = qc.w;

        #pragma unroll
        for (int k = 0; k < 4; ++k) bm[warp][lane * 4 + k] = 0u;
        __syncwarp();

        for (int sgi = 0; sgi < nseg; ++sgi) {
            const int e = seg_e[sgi];
            #pragma unroll 4
            for (int i = seg_s[sgi] + lane; i < e; i += 32) {
                const float4 c = cand[i];
                // byte-identical verified predicate
                const float dot = fmaf(zn, c.z, fmaf(yn, c.y, __fmul_rn(xn, c.x)));
                const float d2  = __fsub_rn(__fadd_rn(sqn, c.w), __fmul_rn(2.0f, dot));
                if (d2 < 256.0f) {
                    const int id = sid[i];
                    atomicOr(&bm[warp][id >> 5], 1u << (id & 31));
                }
            }
        }
        __syncwarp();

        // verified selection: popc prefix over 128 words, ranks {0,16..30}
        int c4[4];
        int lsum = 0;
        #pragma unroll
        for (int k = 0; k < 4; ++k) {
            c4[k] = __popc(bm[warp][lane * 4 + k]);
            lsum += c4[k];
        }
        int incl = lsum;
        #pragma unroll
        for (int off = 1; off < 32; off <<= 1) {
            const int t = __shfl_up_sync(0xffffffffu, incl, off);
            if (lane >= off) incl += t;
        }
        const int cnt = __shfl_sync(0xffffffffu, incl, 31);
        int base = incl - lsum;
        #pragma unroll
        for (int k = 0; k < 4; ++k) {
            cum[warp][lane * 4 + k] = base;
            base += c4[k];
        }
        __syncwarp();

        int own = 0;
        const int t = (lane == 0) ? 0 : lane + 15;
        if (lane < 16 && t < cnt) {
            int lo = 0, hi = 127;
            while (lo < hi) {                       // largest word with cum <= t
                const int mid = (lo + hi + 1) >> 1;
                if (cum[warp][mid] <= t) lo = mid; else hi = mid - 1;
            }
            unsigned w = bm[warp][lo];
            int r = t - cum[warp][lo];
            while (r--) w &= (w - 1u);
            own = (lo << 5) + (__ffs(w) - 1);
        }
        const int h0 = __shfl_sync(0xffffffffu, own, 0);  // center (cnt>=1: self-hit)
        if (lane < 16) g_ids[((bb + qn) << 4) + lane] = (t < cnt) ? own : h0;
        __syncwarp();
    }
}

// ---------------- gathers (unchanged, verified) ----------------
__global__ __launch_bounds__(256) void gather_xyz_kernel(const float* __restrict__ xyz,
                                                         float* __restrict__ out) {
    const int t  = blockIdx.x * 256 + threadIdx.x;    // b(2)|n(12)|k4(2)
    const int k4 = t & 3;
    const int n  = (t >> 2) & (NP - 1);
    const int b  = t >> 14;
    const int bb = b << 12;
    const int4 id4 = reinterpret_cast<const int4*>(g_ids)[t];
    const int o4 = (n << 2) + k4;

    const float* xb = xyz + 3 * bb;
    const float x0 = xb[3 * id4.x], y0 = xb[3 * id4.x + 1], z0 = xb[3 * id4.x + 2];
    const float x1 = xb[3 * id4.y], y1 = xb[3 * id4.y + 1], z1 = xb[3 * id4.y + 2];
    const float x2 = xb[3 * id4.z], y2 = xb[3 * id4.z + 1], z2 = xb[3 * id4.z + 2];
    const float x3 = xb[3 * id4.w], y3 = xb[3 * id4.w + 1], z3 = xb[3 * id4.w + 2];
    float4* o = reinterpret_cast<float4*>(out);
    o[((b * 3 + 0) << 14) + o4] = make_float4(x0, x1, x2, x3);
    o[((b * 3 + 1) << 14) + o4] = make_float4(y0, y1, y2, y3);
    o[((b * 3 + 2) << 14) + o4] = make_float4(z0, z1, z2, z3);
}

__global__ __launch_bounds__(256) void gather_feat_kernel(const float* __restrict__ feat,
                                                          float* __restrict__ out) {
    const int t  = blockIdx.x * 256 + threadIdx.x;    // b(2)|n(12)|k4(2)|cq(2)
    const int cq = t & 3;
    const int k4 = (t >> 2) & 3;
    const int n  = (t >> 4) & (NP - 1);
    const int b  = t >> 16;
    const int bb = b << 12;
    const int4 id4 = reinterpret_cast<const int4*>(g_ids)[((bb + n) << 2) + k4];
    const int o4 = (n << 2) + k4;

    const float4* f0 = reinterpret_cast<const float4*>(feat) + ((bb + id4.x) << 4) + (cq << 2);
    const float4* f1 = reinterpret_cast<const float4*>(feat) + ((bb + id4.y) << 4) + (cq << 2);
    const float4* f2 = reinterpret_cast<const float4*>(feat) + ((bb + id4.z) << 4) + (cq << 2);
    const float4* f3 = reinterpret_cast<const float4*>(feat) + ((bb + id4.w) << 4) + (cq << 2);

    float4* of = reinterpret_cast<float4*>(out) + ((12 + b * 64 + (cq << 4)) << 14) + o4;
    #pragma unroll
    for (int j = 0; j < 4; ++j) {
        const float4 v0 = f0[j], v1 = f1[j], v2 = f2[j], v3 = f3[j];
        of[(4 * j + 0) << 14] = make_float4(v0.x, v1.x, v2.x, v3.x);
        of[(4 * j + 1) << 14] = make_float4(v0.y, v1.y, v2.y, v3.y);
        of[(4 * j + 2) << 14] = make_float4(v0.z, v1.z, v2.z, v3.z);
        of[(4 * j + 3) << 14] = make_float4(v0.w, v1.w, v2.w, v3.w);
    }
}

extern "C" void kernel_launch(void* const* d_in, const int* in_sizes, int n_in,
                              void* d_out, int out_size) {
    const float* xyz  = (const float*)d_in[0];
    const float* feat = (const float*)d_in[1];
    float* out = (float*)d_out;

    count_kernel<<<CBLK, 256>>>(xyz);
    scan_kernel<<<NB, 512>>>();
    scatter_kernel<<<CBLK, 256>>>(xyz);
    query_kernel<<<NB * NCELL2 * SPLIT, 32 * QW>>>();
    gather_xyz_kernel<<<(NB * NP * 4) / 256, 256>>>(xyz, out);
    gather_feat_kernel<<<(NB * NP * KOUT) / 256, 256>>>(feat, out);
}

// round 10
// speedup vs baseline: 1.5333x; 1.5333x over previous
#include <cuda_runtime.h>

// AnnularDilatedKNN: B=4, N=4096, C=64, SAMPLE=16, DILATED_RATE=2 -> NSAMPLE=32, K_out=16
// radius^2 = 256.
//
// R10: R9's query kernel (2-D (z,y) cell pruning, no staging, full occupancy,
// bitmap + verified selection) with R8's BALANCED distribution: warp-per-query
// over the cell-sorted order (block = 16 consecutive sorted queries). Single
// variable changed vs R9 = work distribution.
// Build chain + gathers + predicate + selection byte-identical to rel_err=0.0 code.

#define NB     4
#define NP     4096
#define KOUT   16
#define NCY    20
#define NCZ    20
#define NCELL2 (NCY * NCZ)          // 400
#define CMIN   (-170.0f)
#define INVC   (1.0f / 17.0f)
#define QW     16                   // warps (queries) per query block
#define CBLK   64                   // count/scatter blocks (256 thr), 16 per batch

__device__ float4 g_cand[NB * NP];           // cell-sorted (x,y,z,sq)
__device__ int    g_sid[NB * NP];            // original index per sorted slot
__device__ int    g_pcell[NB * NP];          // cell per original point
__device__ int    g_blkcnt[CBLK * NCELL2];
__device__ int    g_blkbase[CBLK * NCELL2];
__device__ int    g_cstart[NB * (NCELL2 + 1)];
__device__ int    g_ids[NB * NP * KOUT];

__device__ __forceinline__ float sq3(float x, float y, float z) {
    // jnp.sum(xyz*xyz, -1): left-to-right, separately rounded products (no fma).
    return __fadd_rn(__fadd_rn(__fmul_rn(x, x), __fmul_rn(y, y)), __fmul_rn(z, z));
}

__device__ __forceinline__ int cell1(float v) {
    int c = (int)floorf(__fmul_rn(__fadd_rn(v, -CMIN), INVC));
    return min(max(c, 0), NCY - 1);
}

// ---- build 1: per-block cell counts ----
__global__ __launch_bounds__(256) void count_kernel(const float* __restrict__ xyz) {
    __shared__ int sc[NCELL2];
    const int i = blockIdx.x * 256 + threadIdx.x;
    for (int k = threadIdx.x; k < NCELL2; k += 256) sc[k] = 0;
    __syncthreads();
    const float y = xyz[3 * i + 1];
    const float z = xyz[3 * i + 2];
    const int c = cell1(z) * NCY + cell1(y);
    g_pcell[i] = c;
    atomicAdd(&sc[c], 1);
    __syncthreads();
    for (int k = threadIdx.x; k < NCELL2; k += 256)
        g_blkcnt[blockIdx.x * NCELL2 + k] = sc[k];
}

// ---- build 2: per-batch exclusive scan over 400 cells + per-block bases ----
__global__ __launch_bounds__(512) void scan_kernel() {
    __shared__ int wsum[16];
    const int b = blockIdx.x;
    const int tid = threadIdx.x, lane = tid & 31, wid = tid >> 5;

    int cnts[16];
    int tot = 0;
    if (tid < NCELL2) {
        #pragma unroll
        for (int k = 0; k < 16; ++k) {
            cnts[k] = g_blkcnt[(b * 16 + k) * NCELL2 + tid];
            tot += cnts[k];
        }
    }
    int incl = (tid < NCELL2) ? tot : 0;
    #pragma unroll
    for (int off = 1; off < 32; off <<= 1) {
        const int t = __shfl_up_sync(0xffffffffu, incl, off);
        if (lane >= off) incl += t;
    }
    if (lane == 31) wsum[wid] = incl;
    __syncthreads();
    if (wid == 0 && lane < 16) {
        int wv = wsum[lane];
        int wi = wv;
        #pragma unroll
        for (int off = 1; off < 16; off <<= 1) {
            const int t = __shfl_up_sync(0x0000ffffu, wi, off);
            if (lane >= off) wi += t;
        }
        wsum[lane] = wi - wv;
    }
    __syncthreads();
    if (tid < NCELL2) {
        const int excl = (incl - tot) + wsum[wid];
        g_cstart[b * (NCELL2 + 1) + tid] = excl;
        if (tid == NCELL2 - 1) g_cstart[b * (NCELL2 + 1) + NCELL2] = excl + tot; // == NP
        int run = excl;
        #pragma unroll
        for (int k = 0; k < 16; ++k) {
            g_blkbase[(b * 16 + k) * NCELL2 + tid] = run;
            run += cnts[k];
        }
    }
}

// ---- build 3: scatter into cell-sorted order (smem atomics only) ----
__global__ __launch_bounds__(256) void scatter_kernel(const float* __restrict__ xyz) {
    __shared__ int sc[NCELL2];
    __shared__ int sb[NCELL2];
    const int i = blockIdx.x * 256 + threadIdx.x;
    const int b = i >> 12;
    for (int k = threadIdx.x; k < NCELL2; k += 256) {
        sc[k] = 0;
        sb[k] = g_blkbase[blockIdx.x * NCELL2 + k];
    }
    __syncthreads();
    const int c = g_pcell[i];
    const int lr = atomicAdd(&sc[c], 1);
    const float x = xyz[3 * i + 0];
    const float y = xyz[3 * i + 1];
    const float z = xyz[3 * i + 2];
    const int gi = (b << 12) + sb[c] + lr;
    g_cand[gi] = make_float4(x, y, z, sq3(x, y, z));
    g_sid[gi] = i & (NP - 1);
}

// ---- query: warp per SORTED query; 3 contiguous 2-D neighborhood runs ----
__global__ __launch_bounds__(32 * QW) void query_kernel() {
    __shared__ unsigned bm[QW][128];
    __shared__ int cum[QW][128];

    const int warp = threadIdx.x >> 5, lane = threadIdx.x & 31;
    const int p = blockIdx.x * QW + warp;        // sorted position, 0..16383
    const int b = p >> 12;
    const int bb = b << 12;

    const float4 qc = g_cand[p];
    const int qn = g_sid[p];
    const float xn = qc.x, yn = qc.y, zn = qc.z, sqn = qc.w;

    // own cell + neighborhood segments (same rounded cell fn as build)
    const int cy = cell1(yn), cz = cell1(zn);
    const int ylo = max(cy - 1, 0), yhi = min(cy + 1, NCY - 1);
    const int zlo = max(cz - 1, 0), zhi = min(cz + 1, NCZ - 1);
    const int* __restrict__ cs = g_cstart + b * (NCELL2 + 1);
    int seg_s[3], seg_e[3];
    int nseg = 0;
    for (int zz = zlo; zz <= zhi; ++zz) {
        seg_s[nseg] = cs[zz * NCY + ylo];
        seg_e[nseg] = cs[zz * NCY + yhi + 1];
        ++nseg;
    }

    #pragma unroll
    for (int k = 0; k < 4; ++k) bm[warp][lane * 4 + k] = 0u;
    __syncwarp();

    const float4* __restrict__ cand = g_cand + bb;
    const int* __restrict__ sid = g_sid + bb;

    for (int sgi = 0; sgi < nseg; ++sgi) {
        const int e = seg_e[sgi];
        #pragma unroll 4
        for (int i = seg_s[sgi] + lane; i < e; i += 32) {
            const float4 c = cand[i];
            // byte-identical verified predicate
            const float dot = fmaf(zn, c.z, fmaf(yn, c.y, __fmul_rn(xn, c.x)));
            const float d2  = __fsub_rn(__fadd_rn(sqn, c.w), __fmul_rn(2.0f, dot));
            if (d2 < 256.0f) {
                const int id = sid[i];
                atomicOr(&bm[warp][id >> 5], 1u << (id & 31));
            }
        }
    }
    __syncwarp();

    // verified selection: popc prefix over 128 words, ranks {0,16..30}
    int c4[4];
    int lsum = 0;
    #pragma unroll
    for (int k = 0; k < 4; ++k) {
        c4[k] = __popc(bm[warp][lane * 4 + k]);
        lsum += c4[k];
    }
    int incl = lsum;
    #pragma unroll
    for (int off = 1; off < 32; off <<= 1) {
        const int t = __shfl_up_sync(0xffffffffu, incl, off);
        if (lane >= off) incl += t;
    }
    const int cnt = __shfl_sync(0xffffffffu, incl, 31);
    int base = incl - lsum;
    #pragma unroll
    for (int k = 0; k < 4; ++k) {
        cum[warp][lane * 4 + k] = base;
        base += c4[k];
    }
    __syncwarp();

    int own = 0;
    const int t = (lane == 0) ? 0 : lane + 15;
    if (lane < 16 && t < cnt) {
        int lo = 0, hi = 127;
        while (lo < hi) {                        // largest word with cum <= t
            const int mid = (lo + hi + 1) >> 1;
            if (cum[warp][mid] <= t) lo = mid; else hi = mid - 1;
        }
        unsigned w = bm[warp][lo];
        int r = t - cum[warp][lo];
        while (r--) w &= (w - 1u);
        own = (lo << 5) + (__ffs(w) - 1);
    }
    const int h0 = __shfl_sync(0xffffffffu, own, 0);  // center (cnt>=1: self-hit)
    if (lane < 16) g_ids[((bb + qn) << 4) + lane] = (t < cnt) ? own : h0;
}

// ---------------- gathers (unchanged, verified) ----------------
__global__ __launch_bounds__(256) void gather_xyz_kernel(const float* __restrict__ xyz,
                                                         float* __restrict__ out) {
    const int t  = blockIdx.x * 256 + threadIdx.x;    // b(2)|n(12)|k4(2)
    const int k4 = t & 3;
    const int n  = (t >> 2) & (NP - 1);
    const int b  = t >> 14;
    const int bb = b << 12;
    const int4 id4 = reinterpret_cast<const int4*>(g_ids)[t];
    const int o4 = (n << 2) + k4;

    const float* xb = xyz + 3 * bb;
    const float x0 = xb[3 * id4.x], y0 = xb[3 * id4.x + 1], z0 = xb[3 * id4.x + 2];
    const float x1 = xb[3 * id4.y], y1 = xb[3 * id4.y + 1], z1 = xb[3 * id4.y + 2];
    const float x2 = xb[3 * id4.z], y2 = xb[3 * id4.z + 1], z2 = xb[3 * id4.z + 2];
    const float x3 = xb[3 * id4.w], y3 = xb[3 * id4.w + 1], z3 = xb[3 * id4.w + 2];
    float4* o = reinterpret_cast<float4*>(out);
    o[((b * 3 + 0) << 14) + o4] = make_float4(x0, x1, x2, x3);
    o[((b * 3 + 1) << 14) + o4] = make_float4(y0, y1, y2, y3);
    o[((b * 3 + 2) << 14) + o4] = make_float4(z0, z1, z2, z3);
}

__global__ __launch_bounds__(256) void gather_feat_kernel(const float* __restrict__ feat,
                                                          float* __restrict__ out) {
    const int t  = blockIdx.x * 256 + threadIdx.x;    // b(2)|n(12)|k4(2)|cq(2)
    const int cq = t & 3;
    const int k4 = (t >> 2) & 3;
    const int n  = (t >> 4) & (NP - 1);
    const int b  = t >> 16;
    const int bb = b << 12;
    const int4 id4 = reinterpret_cast<const int4*>(g_ids)[((bb + n) << 2) + k4];
    const int o4 = (n << 2) + k4;

    const float4* f0 = reinterpret_cast<const float4*>(feat) + ((bb + id4.x) << 4) + (cq << 2);
    const float4* f1 = reinterpret_cast<const float4*>(feat) + ((bb + id4.y) << 4) + (cq << 2);
    const float4* f2 = reinterpret_cast<const float4*>(feat) + ((bb + id4.z) << 4) + (cq << 2);
    const float4* f3 = reinterpret_cast<const float4*>(feat) + ((bb + id4.w) << 4) + (cq << 2);

    float4* of = reinterpret_cast<float4*>(out) + ((12 + b * 64 + (cq << 4)) << 14) + o4;
    #pragma unroll
    for (int j = 0; j < 4; ++j) {
        const float4 v0 = f0[j], v1 = f1[j], v2 = f2[j], v3 = f3[j];
        of[(4 * j + 0) << 14] = make_float4(v0.x, v1.x, v2.x, v3.x);
        of[(4 * j + 1) << 14] = make_float4(v0.y, v1.y, v2.y, v3.y);
        of[(4 * j + 2) << 14] = make_float4(v0.z, v1.z, v2.z, v3.z);
        of[(4 * j + 3) << 14] = make_float4(v0.w, v1.w, v2.w, v3.w);
    }
}

extern "C" void kernel_launch(void* const* d_in, const int* in_sizes, int n_in,
                              void* d_out, int out_size) {
    const float* xyz  = (const float*)d_in[0];
    const float* feat = (const float*)d_in[1];
    float* out = (float*)d_out;

    count_kernel<<<CBLK, 256>>>(xyz);
    scan_kernel<<<NB, 512>>>();
    scatter_kernel<<<CBLK, 256>>>(xyz);
    query_kernel<<<(NB * NP) / QW, 32 * QW>>>();
    gather_xyz_kernel<<<(NB * NP * 4) / 256, 256>>>(xyz, out);
    gather_feat_kernel<<<(NB * NP * KOUT) / 256, 256>>>(feat, out);
}